// round 2
// baseline (speedup 1.0000x reference)
#include <cuda_runtime.h>
#include <cstdint>

// Problem constants
#define Bn 8
#define Cn 64
#define Hn 256
#define Wn 256
#define TM 64          // rows per CTA
#define KT 16          // k-chunk
#define NTHREADS 256

typedef unsigned long long ull;

// Packed fp32x2 FMA (Blackwell): d = a*b + d on pairs
#define FFMA2(d, a, bb) asm("fma.rn.f32x2 %0, %1, %2, %0;" : "+l"(d) : "l"(a), "l"(bb))
#define PACK2(d, s)     asm("mov.b64 %0, {%1, %1};" : "=l"(d) : "f"(s))
#define UNPACK2(lo, hi, s) asm("mov.b64 {%0, %1}, %2;" : "=f"(lo), "=f"(hi) : "l"(s))

__device__ __forceinline__ void cp_async16(uint32_t dst, const float* src) {
    asm volatile("cp.async.cg.shared.global [%0], [%1], 16;" :: "r"(dst), "l"(src));
}

// 64x256 fp32 GEMM: acc[row 8][col 8] per thread. Rows = ty*8..+7.
// Cols: A-half = tx*4..tx*4+3, B-half = 128 + tx*4..+3 (as f32x2 pairs).
__device__ __forceinline__ void gemm64(const float* __restrict__ gw,
                                       const float* __restrict__ xs,
                                       const float* __restrict__ ws,
                                       uint32_t ws_s,
                                       int tid, int tx, int ty,
                                       ull accA[8][2], ull accB[8][2])
{
    #pragma unroll
    for (int i = 0; i < 8; ++i) {
        accA[i][0] = 0ull; accA[i][1] = 0ull;
        accB[i][0] = 0ull; accB[i][1] = 0ull;
    }

    // prologue: chunk 0 -> buf 0
    #pragma unroll
    for (int j = 0; j < 4; ++j)
        cp_async16(ws_s + (uint32_t)((tid + j * 256) * 16), gw + (tid + j * 256) * 4);
    asm volatile("cp.async.commit_group;");

    #pragma unroll 1
    for (int kc = 0; kc < 16; ++kc) {
        const int buf = kc & 1;
        if (kc < 15) {
            const float* src = gw + (kc + 1) * KT * Wn;
            const uint32_t d0 = ws_s + (uint32_t)((buf ^ 1) * KT * Wn * 4);
            #pragma unroll
            for (int j = 0; j < 4; ++j)
                cp_async16(d0 + (uint32_t)((tid + j * 256) * 16), src + (tid + j * 256) * 4);
            asm volatile("cp.async.commit_group;");
            asm volatile("cp.async.wait_group 1;");
        } else {
            asm volatile("cp.async.wait_group 0;");
        }
        __syncthreads();

        const float* wb = ws + buf * KT * Wn;
        #pragma unroll
        for (int kk2 = 0; kk2 < 8; ++kk2) {
            const int w0 = kc * KT + kk2 * 2;
            float2 xp[8];
            #pragma unroll
            for (int i = 0; i < 8; ++i)
                xp[i] = *reinterpret_cast<const float2*>(xs + (ty * 8 + i) * Wn + w0);
            #pragma unroll
            for (int t = 0; t < 2; ++t) {
                const ulonglong2* wrow =
                    reinterpret_cast<const ulonglong2*>(wb + (kk2 * 2 + t) * Wn);
                ulonglong2 wA = wrow[tx];
                ulonglong2 wB = wrow[32 + tx];
                #pragma unroll
                for (int i = 0; i < 8; ++i) {
                    float xv = t ? xp[i].y : xp[i].x;
                    ull xd; PACK2(xd, xv);
                    FFMA2(accA[i][0], xd, wA.x);
                    FFMA2(accA[i][1], xd, wA.y);
                    FFMA2(accB[i][0], xd, wB.x);
                    FFMA2(accB[i][1], xd, wB.y);
                }
            }
        }
        __syncthreads();
    }
}

extern __shared__ float smem_dyn[];

__global__ void __launch_bounds__(NTHREADS, 1) axile_attn_kernel(
    const float* __restrict__ x,  const float* __restrict__ qw,
    const float* __restrict__ kw, const float* __restrict__ vw,
    const float* __restrict__ qb, const float* __restrict__ kb,
    const float* __restrict__ vb, float* __restrict__ out)
{
    float* xs = smem_dyn;                 // [64][256]
    float* ws = xs + TM * Wn;             // [2][16][256]
    float* Ls = ws + 2 * KT * Wn;         // [64][256]

    const int tid = threadIdx.x;
    const int tx  = tid & 31;
    const int ty  = tid >> 5;
    const int h0  = blockIdx.x * TM;
    const int c   = blockIdx.y;
    const int b   = blockIdx.z;

    // ---- load x tile (coalesced float4 copy) ----
    {
        const float4* xsrc = reinterpret_cast<const float4*>(
            x + (size_t)(((b * Cn + c) * Hn + h0)) * Wn);
        float4* xs4 = reinterpret_cast<float4*>(xs);
        #pragma unroll
        for (int j = 0; j < (TM * Wn / 4) / NTHREADS; ++j)
            xs4[tid + j * NTHREADS] = xsrc[tid + j * NTHREADS];
    }
    __syncthreads();

    const uint32_t ws_s = (uint32_t)__cvta_generic_to_shared(ws);
    const int cb = c * Hn * Wn + h0 * Wn;  // bias base (c, h0 rows)
    float4* Ls4 = reinterpret_cast<float4*>(Ls);

    ull accA[8][2], accB[8][2];

    // =================== Q = x @ Wq + bq -> Ls ===================
    gemm64(qw + (size_t)c * Wn * Wn, xs, ws, ws_s, tid, tx, ty, accA, accB);
    #pragma unroll
    for (int i = 0; i < 8; ++i) {
        const int row = ty * 8 + i;
        const float4* br = reinterpret_cast<const float4*>(qb + cb + row * Wn);
        float4 bA = br[tx], bB = br[32 + tx];
        float4 vA, vB;
        UNPACK2(vA.x, vA.y, accA[i][0]); UNPACK2(vA.z, vA.w, accA[i][1]);
        UNPACK2(vB.x, vB.y, accB[i][0]); UNPACK2(vB.z, vB.w, accB[i][1]);
        vA.x += bA.x; vA.y += bA.y; vA.z += bA.z; vA.w += bA.w;
        vB.x += bB.x; vB.y += bB.y; vB.z += bB.z; vB.w += bB.w;
        Ls4[row * 64 + tx]      = vA;
        Ls4[row * 64 + 32 + tx] = vB;
    }

    // ============ K pass: logits = Q*(K+bk); softmax -> Ls ============
    gemm64(kw + (size_t)c * Wn * Wn, xs, ws, ws_s, tid, tx, ty, accA, accB);
    #pragma unroll
    for (int i = 0; i < 8; ++i) {
        const int row = ty * 8 + i;
        const float4* br = reinterpret_cast<const float4*>(kb + cb + row * Wn);
        float4 bA = br[tx], bB = br[32 + tx];
        float4 qA = Ls4[row * 64 + tx];
        float4 qB = Ls4[row * 64 + 32 + tx];
        float l[8];
        float k0, k1;
        UNPACK2(k0, k1, accA[i][0]); l[0] = qA.x * (k0 + bA.x); l[1] = qA.y * (k1 + bA.y);
        UNPACK2(k0, k1, accA[i][1]); l[2] = qA.z * (k0 + bA.z); l[3] = qA.w * (k1 + bA.w);
        UNPACK2(k0, k1, accB[i][0]); l[4] = qB.x * (k0 + bB.x); l[5] = qB.y * (k1 + bB.y);
        UNPACK2(k0, k1, accB[i][1]); l[6] = qB.z * (k0 + bB.z); l[7] = qB.w * (k1 + bB.w);

        float mx = l[0];
        #pragma unroll
        for (int j = 1; j < 8; ++j) mx = fmaxf(mx, l[j]);
        #pragma unroll
        for (int off = 16; off; off >>= 1)
            mx = fmaxf(mx, __shfl_xor_sync(0xffffffffu, mx, off));

        float e[8];
        float s = 0.f;
        #pragma unroll
        for (int j = 0; j < 8; ++j) { e[j] = __expf(l[j] - mx); s += e[j]; }
        #pragma unroll
        for (int off = 16; off; off >>= 1)
            s += __shfl_xor_sync(0xffffffffu, s, off);
        const float r = 1.0f / s;

        float4 pA, pB;
        pA.x = e[0] * r; pA.y = e[1] * r; pA.z = e[2] * r; pA.w = e[3] * r;
        pB.x = e[4] * r; pB.y = e[5] * r; pB.z = e[6] * r; pB.w = e[7] * r;
        Ls4[row * 64 + tx]      = pA;
        Ls4[row * 64 + 32 + tx] = pB;
    }

    // =============== V pass: out = P * (V + bv) ===============
    gemm64(vw + (size_t)c * Wn * Wn, xs, ws, ws_s, tid, tx, ty, accA, accB);
    #pragma unroll
    for (int i = 0; i < 8; ++i) {
        const int row = ty * 8 + i;
        const float4* br = reinterpret_cast<const float4*>(vb + cb + row * Wn);
        float4 bA = br[tx], bB = br[32 + tx];
        float4 pA = Ls4[row * 64 + tx];
        float4 pB = Ls4[row * 64 + 32 + tx];
        float v0, v1;
        float4 oA, oB;
        UNPACK2(v0, v1, accA[i][0]); oA.x = pA.x * (v0 + bA.x); oA.y = pA.y * (v1 + bA.y);
        UNPACK2(v0, v1, accA[i][1]); oA.z = pA.z * (v0 + bA.z); oA.w = pA.w * (v1 + bA.w);
        UNPACK2(v0, v1, accB[i][0]); oB.x = pB.x * (v0 + bB.x); oB.y = pB.y * (v1 + bB.y);
        UNPACK2(v0, v1, accB[i][1]); oB.z = pB.z * (v0 + bB.z); oB.w = pB.w * (v1 + bB.w);

        float4* og = reinterpret_cast<float4*>(
            out + (size_t)(((b * Cn + c) * Hn + h0 + row)) * Wn);
        og[tx]      = oA;
        og[32 + tx] = oB;
    }
}

extern "C" void kernel_launch(void* const* d_in, const int* in_sizes, int n_in,
                              void* d_out, int out_size) {
    const float* x  = (const float*)d_in[0];
    const float* qw = (const float*)d_in[1];
    const float* kw = (const float*)d_in[2];
    const float* vw = (const float*)d_in[3];
    const float* qb = (const float*)d_in[4];
    const float* kb = (const float*)d_in[5];
    const float* vb = (const float*)d_in[6];
    float* out = (float*)d_out;

    constexpr int SMEM_BYTES = (TM * Wn + 2 * KT * Wn + TM * Wn) * 4;  // 160 KB
    cudaFuncSetAttribute(axile_attn_kernel,
                         cudaFuncAttributeMaxDynamicSharedMemorySize, SMEM_BYTES);
    dim3 grid(Hn / TM, Cn, Bn);
    axile_attn_kernel<<<grid, NTHREADS, SMEM_BYTES>>>(x, qw, kw, vw, qb, kb, vb, out);
}

// round 3
// speedup vs baseline: 1.0093x; 1.0093x over previous
#include <cuda_runtime.h>
#include <cstdint>

// Problem constants
#define Bn 8
#define Cn 64
#define Hn 256
#define Wn 256
#define TM 64          // rows per CTA
#define KT 32          // k-chunk (32 k-values per smem stage)
#define NTHREADS 512
#define RPT 4          // rows per thread

typedef unsigned long long ull;

// Packed fp32x2 FMA (Blackwell): d = a*b + d on pairs
#define FFMA2(d, a, bb) asm("fma.rn.f32x2 %0, %1, %2, %0;" : "+l"(d) : "l"(a), "l"(bb))
#define PACK2(d, s)     asm("mov.b64 %0, {%1, %1};" : "=l"(d) : "f"(s))
#define UNPACK2(lo, hi, s) asm("mov.b64 {%0, %1}, %2;" : "=f"(lo), "=f"(hi) : "l"(s))

__device__ __forceinline__ void cp_async16(uint32_t dst, const float* src) {
    asm volatile("cp.async.cg.shared.global [%0], [%1], 16;" :: "r"(dst), "l"(src));
}

// 64x256 fp32 GEMM: per-thread acc = 4 rows x 8 cols (as f32x2 pairs).
// Rows = ty*4..+3. Cols: A-half = tx*4..+3, B-half = 128+tx*4..+3.
__device__ __forceinline__ void gemm64(const float* __restrict__ gw,
                                       const float* __restrict__ xs,
                                       const float* __restrict__ ws,
                                       uint32_t ws_s,
                                       int tid, int tx, int ty,
                                       ull accA[RPT][2], ull accB[RPT][2])
{
    #pragma unroll
    for (int i = 0; i < RPT; ++i) {
        accA[i][0] = 0ull; accA[i][1] = 0ull;
        accB[i][0] = 0ull; accB[i][1] = 0ull;
    }

    // prologue: chunk 0 -> buf 0   (KT*Wn floats = 2048 float4, 4 per thread)
    #pragma unroll
    for (int j = 0; j < 4; ++j)
        cp_async16(ws_s + (uint32_t)((tid + j * NTHREADS) * 16),
                   gw + (tid + j * NTHREADS) * 4);
    asm volatile("cp.async.commit_group;");

    #pragma unroll 1
    for (int kc = 0; kc < Wn / KT; ++kc) {      // 8 chunks
        const int buf = kc & 1;
        asm volatile("cp.async.wait_group 0;");
        __syncthreads();   // single barrier: data visible AND prev buffer fully consumed

        if (kc < Wn / KT - 1) {
            const float* src = gw + (kc + 1) * KT * Wn;
            const uint32_t d0 = ws_s + (uint32_t)((buf ^ 1) * KT * Wn * 4);
            #pragma unroll
            for (int j = 0; j < 4; ++j)
                cp_async16(d0 + (uint32_t)((tid + j * NTHREADS) * 16),
                           src + (tid + j * NTHREADS) * 4);
            asm volatile("cp.async.commit_group;");
        }

        const float* wb = ws + buf * KT * Wn;
        #pragma unroll
        for (int kk2 = 0; kk2 < KT / 2; ++kk2) {
            const int w0 = kc * KT + kk2 * 2;
            float2 xp[RPT];
            #pragma unroll
            for (int i = 0; i < RPT; ++i)
                xp[i] = *reinterpret_cast<const float2*>(xs + (ty * RPT + i) * Wn + w0);
            #pragma unroll
            for (int t = 0; t < 2; ++t) {
                const ulonglong2* wrow =
                    reinterpret_cast<const ulonglong2*>(wb + (kk2 * 2 + t) * Wn);
                ulonglong2 wA = wrow[tx];
                ulonglong2 wB = wrow[32 + tx];
                #pragma unroll
                for (int i = 0; i < RPT; ++i) {
                    float xv = t ? xp[i].y : xp[i].x;
                    ull xd; PACK2(xd, xv);
                    FFMA2(accA[i][0], xd, wA.x);
                    FFMA2(accA[i][1], xd, wA.y);
                    FFMA2(accB[i][0], xd, wB.x);
                    FFMA2(accB[i][1], xd, wB.y);
                }
            }
        }
    }
    __syncthreads();   // all compute done before epilogue rewrites Ls / next gemm prefetch
}

extern __shared__ float smem_dyn[];

__global__ void __launch_bounds__(NTHREADS, 1) axile_attn_kernel(
    const float* __restrict__ x,  const float* __restrict__ qw,
    const float* __restrict__ kw, const float* __restrict__ vw,
    const float* __restrict__ qb, const float* __restrict__ kb,
    const float* __restrict__ vb, float* __restrict__ out)
{
    float* xs = smem_dyn;                 // [64][256]   64 KB
    float* ws = xs + TM * Wn;             // [2][32][256] 64 KB
    float* Ls = ws + 2 * KT * Wn;         // [64][256]   64 KB

    const int tid = threadIdx.x;
    const int tx  = tid & 31;
    const int ty  = tid >> 5;             // warp id, 0..15
    const int h0  = blockIdx.x * TM;
    const int c   = blockIdx.y;
    const int b   = blockIdx.z;

    // ---- load x tile (coalesced float4 copy) ----
    {
        const float4* xsrc = reinterpret_cast<const float4*>(
            x + (size_t)(((b * Cn + c) * Hn + h0)) * Wn);
        float4* xs4 = reinterpret_cast<float4*>(xs);
        #pragma unroll
        for (int j = 0; j < (TM * Wn / 4) / NTHREADS; ++j)
            xs4[tid + j * NTHREADS] = xsrc[tid + j * NTHREADS];
    }
    __syncthreads();

    const uint32_t ws_s = (uint32_t)__cvta_generic_to_shared(ws);
    const int cb = c * Hn * Wn + h0 * Wn;  // bias base (c, h0 rows)
    float4* Ls4 = reinterpret_cast<float4*>(Ls);

    ull accA[RPT][2], accB[RPT][2];

    // =================== Q = x @ Wq + bq -> Ls ===================
    gemm64(qw + (size_t)c * Wn * Wn, xs, ws, ws_s, tid, tx, ty, accA, accB);
    #pragma unroll
    for (int i = 0; i < RPT; ++i) {
        const int row = ty * RPT + i;
        const float4* br = reinterpret_cast<const float4*>(qb + cb + row * Wn);
        float4 bA = br[tx], bB = br[32 + tx];
        float4 vA, vB;
        UNPACK2(vA.x, vA.y, accA[i][0]); UNPACK2(vA.z, vA.w, accA[i][1]);
        UNPACK2(vB.x, vB.y, accB[i][0]); UNPACK2(vB.z, vB.w, accB[i][1]);
        vA.x += bA.x; vA.y += bA.y; vA.z += bA.z; vA.w += bA.w;
        vB.x += bB.x; vB.y += bB.y; vB.z += bB.z; vB.w += bB.w;
        Ls4[row * 64 + tx]      = vA;
        Ls4[row * 64 + 32 + tx] = vB;
    }

    // ============ K pass: logits = Q*(K+bk); softmax -> Ls ============
    gemm64(kw + (size_t)c * Wn * Wn, xs, ws, ws_s, tid, tx, ty, accA, accB);
    #pragma unroll
    for (int i = 0; i < RPT; ++i) {
        const int row = ty * RPT + i;
        const float4* br = reinterpret_cast<const float4*>(kb + cb + row * Wn);
        float4 bA = br[tx], bB = br[32 + tx];
        float4 qA = Ls4[row * 64 + tx];
        float4 qB = Ls4[row * 64 + 32 + tx];
        float l[8];
        float k0, k1;
        UNPACK2(k0, k1, accA[i][0]); l[0] = qA.x * (k0 + bA.x); l[1] = qA.y * (k1 + bA.y);
        UNPACK2(k0, k1, accA[i][1]); l[2] = qA.z * (k0 + bA.z); l[3] = qA.w * (k1 + bA.w);
        UNPACK2(k0, k1, accB[i][0]); l[4] = qB.x * (k0 + bB.x); l[5] = qB.y * (k1 + bB.y);
        UNPACK2(k0, k1, accB[i][1]); l[6] = qB.z * (k0 + bB.z); l[7] = qB.w * (k1 + bB.w);

        float mx = l[0];
        #pragma unroll
        for (int j = 1; j < 8; ++j) mx = fmaxf(mx, l[j]);
        #pragma unroll
        for (int off = 16; off; off >>= 1)
            mx = fmaxf(mx, __shfl_xor_sync(0xffffffffu, mx, off));

        float e[8];
        float s = 0.f;
        #pragma unroll
        for (int j = 0; j < 8; ++j) { e[j] = __expf(l[j] - mx); s += e[j]; }
        #pragma unroll
        for (int off = 16; off; off >>= 1)
            s += __shfl_xor_sync(0xffffffffu, s, off);
        const float r = 1.0f / s;

        float4 pA, pB;
        pA.x = e[0] * r; pA.y = e[1] * r; pA.z = e[2] * r; pA.w = e[3] * r;
        pB.x = e[4] * r; pB.y = e[5] * r; pB.z = e[6] * r; pB.w = e[7] * r;
        Ls4[row * 64 + tx]      = pA;
        Ls4[row * 64 + 32 + tx] = pB;
    }

    // =============== V pass: out = P * (V + bv) ===============
    gemm64(vw + (size_t)c * Wn * Wn, xs, ws, ws_s, tid, tx, ty, accA, accB);
    #pragma unroll
    for (int i = 0; i < RPT; ++i) {
        const int row = ty * RPT + i;
        const float4* br = reinterpret_cast<const float4*>(vb + cb + row * Wn);
        float4 bA = br[tx], bB = br[32 + tx];
        float4 pA = Ls4[row * 64 + tx];
        float4 pB = Ls4[row * 64 + 32 + tx];
        float v0, v1;
        float4 oA, oB;
        UNPACK2(v0, v1, accA[i][0]); oA.x = pA.x * (v0 + bA.x); oA.y = pA.y * (v1 + bA.y);
        UNPACK2(v0, v1, accA[i][1]); oA.z = pA.z * (v0 + bA.z); oA.w = pA.w * (v1 + bA.w);
        UNPACK2(v0, v1, accB[i][0]); oB.x = pB.x * (v0 + bB.x); oB.y = pB.y * (v1 + bB.y);
        UNPACK2(v0, v1, accB[i][1]); oB.z = pB.z * (v0 + bB.z); oB.w = pB.w * (v1 + bB.w);

        float4* og = reinterpret_cast<float4*>(
            out + (size_t)(((b * Cn + c) * Hn + h0 + row)) * Wn);
        og[tx]      = oA;
        og[32 + tx] = oB;
    }
}

extern "C" void kernel_launch(void* const* d_in, const int* in_sizes, int n_in,
                              void* d_out, int out_size) {
    const float* x  = (const float*)d_in[0];
    const float* qw = (const float*)d_in[1];
    const float* kw = (const float*)d_in[2];
    const float* vw = (const float*)d_in[3];
    const float* qb = (const float*)d_in[4];
    const float* kb = (const float*)d_in[5];
    const float* vb = (const float*)d_in[6];
    float* out = (float*)d_out;

    constexpr int SMEM_BYTES = (TM * Wn + 2 * KT * Wn + TM * Wn) * 4;  // 192 KB
    cudaFuncSetAttribute(axile_attn_kernel,
                         cudaFuncAttributeMaxDynamicSharedMemorySize, SMEM_BYTES);
    dim3 grid(Hn / TM, Cn, Bn);
    axile_attn_kernel<<<grid, NTHREADS, SMEM_BYTES>>>(x, qw, kw, vw, qb, kb, vb, out);
}